// round 2
// baseline (speedup 1.0000x reference)
#include <cuda_runtime.h>
#include <cstdint>

// Shapes (fixed by problem)
#define Bz 16
#define Nn 1024
#define Cc 768
#define Dd 384

// GEMM tiling
#define BM 128
#define BN 128
#define BK 16
#define TM 8
#define TN 8

// Static device scratch (no allocations allowed)
__device__ __align__(16) float g_tpg[(size_t)Bz * Nn * (3 * Dd)];     // theta|phi|g, ld = 1152
__device__ __align__(16) float g_attn[(size_t)Bz * Nn * Nn];          // scores / softmax
__device__ __align__(16) float g_od[(size_t)Bz * Nn * Dd];            // attn @ g

// ---------------------------------------------------------------------------
// Loaders: tile is BM(=BN)=128 x BK=16. 2048 floats = 512 float4; 256 threads
// load 2 float4 each.
// ---------------------------------------------------------------------------

// Global [rows x K] row-major (K minor) -> S[k][m] (transposed store)
__device__ __forceinline__ void load_trans(float (*S)[BM], const float* __restrict__ g,
                                           int ldg, int tid) {
#pragma unroll
    for (int u = 0; u < 2; u++) {
        int idx = tid + u * 256;
        int m  = idx >> 2;            // 0..127
        int c4 = (idx & 3) * 4;       // 0,4,8,12
        float4 v = *(const float4*)(g + (size_t)m * ldg + c4);
        S[c4 + 0][m] = v.x;
        S[c4 + 1][m] = v.y;
        S[c4 + 2][m] = v.z;
        S[c4 + 3][m] = v.w;
    }
}

// Global [K x cols] row-major (cols minor) -> S[k][j] (direct store)
__device__ __forceinline__ void load_direct(float (*S)[BN], const float* __restrict__ g,
                                            int ldg, int tid) {
#pragma unroll
    for (int u = 0; u < 2; u++) {
        int idx = tid + u * 256;
        int k = idx >> 5;             // 0..15
        int j = (idx & 31) * 4;       // 0..124
        *(float4*)(&S[k][j]) = *(const float4*)(g + (size_t)k * ldg + j);
    }
}

// ---------------------------------------------------------------------------
// Inner product on the tile: each thread does 8x8 FMAs per k, BK=16 steps.
// ---------------------------------------------------------------------------
__device__ __forceinline__ void mma_tile(const float (*As)[BM], const float (*Bs)[BN],
                                         float acc[TM][TN], int ty, int tx) {
#pragma unroll
    for (int k = 0; k < BK; k++) {
        float4 a0 = *(const float4*)(&As[k][ty * TM]);
        float4 a1 = *(const float4*)(&As[k][ty * TM + 4]);
        float4 b0 = *(const float4*)(&Bs[k][tx * TN]);
        float4 b1 = *(const float4*)(&Bs[k][tx * TN + 4]);
        float a[TM] = {a0.x, a0.y, a0.z, a0.w, a1.x, a1.y, a1.z, a1.w};
        float b[TN] = {b0.x, b0.y, b0.z, b0.w, b1.x, b1.y, b1.z, b1.w};
#pragma unroll
        for (int i = 0; i < TM; i++)
#pragma unroll
            for (int j = 0; j < TN; j++)
                acc[i][j] = fmaf(a[i], b[j], acc[i][j]);
    }
}

// ---------------------------------------------------------------------------
// Kernel 1: fused projections.  tpg[M,1152] = x[M,768] @ [Wt|Wp|Wg] + bias
// grid: (16384/128, 1152/128) = (128, 9)
// ---------------------------------------------------------------------------
__global__ __launch_bounds__(256, 2) void k_proj(
    const float* __restrict__ x,
    const float* __restrict__ Wt, const float* __restrict__ bt,
    const float* __restrict__ Wp, const float* __restrict__ bp,
    const float* __restrict__ Wg, const float* __restrict__ bg)
{
    __shared__ __align__(16) float As[BK][BM];
    __shared__ __align__(16) float Bs[BK][BN];
    const int tid = threadIdx.x;
    const int m0 = blockIdx.x * BM;
    const int n0 = blockIdx.y * BN;      // 0..1151, tile fits in one 384-segment
    const int seg = n0 / Dd;
    const int nW  = n0 % Dd;
    const float* W    = (seg == 0) ? Wt : (seg == 1) ? Wp : Wg;
    const float* bias = (seg == 0) ? bt : (seg == 1) ? bp : bg;

    float acc[TM][TN] = {};
    const int ty = tid >> 4, tx = tid & 15;

    for (int k0 = 0; k0 < Cc; k0 += BK) {
        load_trans(As, x + (size_t)m0 * Cc + k0, Cc, tid);
        load_direct(Bs, W + (size_t)k0 * Dd + nW, Dd, tid);
        __syncthreads();
        mma_tile(As, Bs, acc, ty, tx);
        __syncthreads();
    }

    const int r0 = m0 + ty * TM;
    const int c0 = n0 + tx * TN;
#pragma unroll
    for (int i = 0; i < TM; i++) {
        float* dst = g_tpg + (size_t)(r0 + i) * (3 * Dd) + c0;
#pragma unroll
        for (int j = 0; j < TN; j++)
            dst[j] = acc[i][j] + bias[nW + tx * TN + j];
    }
}

// ---------------------------------------------------------------------------
// Kernel 2: scores.  attn[b,i,j] = (theta_b @ phi_b^T)[i,j] * adj[b,i,j]
// grid: (8, 8, 16)
// ---------------------------------------------------------------------------
__global__ __launch_bounds__(256, 2) void k_score(const float* __restrict__ adj)
{
    __shared__ __align__(16) float As[BK][BM];
    __shared__ __align__(16) float Bs[BK][BN];
    const int tid = threadIdx.x;
    const int b  = blockIdx.z;
    const int i0 = blockIdx.x * BM;
    const int j0 = blockIdx.y * BN;

    const float* th = g_tpg + ((size_t)b * Nn + i0) * (3 * Dd);         // theta rows
    const float* ph = g_tpg + ((size_t)b * Nn + j0) * (3 * Dd) + Dd;    // phi rows

    float acc[TM][TN] = {};
    const int ty = tid >> 4, tx = tid & 15;

    for (int k0 = 0; k0 < Dd; k0 += BK) {
        load_trans(As, th + k0, 3 * Dd, tid);
        load_trans((float(*)[BM])Bs, ph + k0, 3 * Dd, tid);
        __syncthreads();
        mma_tile(As, Bs, acc, ty, tx);
        __syncthreads();
    }

    const size_t base = (size_t)b * Nn * Nn;
    const int r0 = i0 + ty * TM;
    const int c0 = j0 + tx * TN;
#pragma unroll
    for (int i = 0; i < TM; i++) {
        const size_t ro = base + (size_t)(r0 + i) * Nn + c0;
#pragma unroll
        for (int j = 0; j < TN; j++)
            g_attn[ro + j] = acc[i][j] * adj[ro + j];
    }
}

// ---------------------------------------------------------------------------
// Kernel 3: row softmax over last dim (1024). One block per row, 256 threads,
// one float4 per thread.
// ---------------------------------------------------------------------------
__global__ __launch_bounds__(256) void k_softmax()
{
    const size_t row = blockIdx.x;
    float4* p = (float4*)(g_attn + row * Nn);
    float4 v = p[threadIdx.x];

    float m = fmaxf(fmaxf(v.x, v.y), fmaxf(v.z, v.w));
#pragma unroll
    for (int o = 16; o; o >>= 1) m = fmaxf(m, __shfl_xor_sync(0xffffffffu, m, o));
    __shared__ float red[8];
    const int warp = threadIdx.x >> 5;
    if ((threadIdx.x & 31) == 0) red[warp] = m;
    __syncthreads();
    float bm = red[0];
#pragma unroll
    for (int i = 1; i < 8; i++) bm = fmaxf(bm, red[i]);
    __syncthreads();

    v.x = __expf(v.x - bm);
    v.y = __expf(v.y - bm);
    v.z = __expf(v.z - bm);
    v.w = __expf(v.w - bm);
    float s = v.x + v.y + v.z + v.w;
#pragma unroll
    for (int o = 16; o; o >>= 1) s += __shfl_xor_sync(0xffffffffu, s, o);
    if ((threadIdx.x & 31) == 0) red[warp] = s;
    __syncthreads();
    float tot = red[0];
#pragma unroll
    for (int i = 1; i < 8; i++) tot += red[i];

    const float inv = 1.0f / tot;
    v.x *= inv; v.y *= inv; v.z *= inv; v.w *= inv;
    p[threadIdx.x] = v;
}

// ---------------------------------------------------------------------------
// Kernel 4: od[b,i,:] = attn[b,i,:] @ g_b   (M=1024, N=384, K=1024 per batch)
// grid: (8, 3, 16)
// ---------------------------------------------------------------------------
__global__ __launch_bounds__(256, 2) void k_av()
{
    __shared__ __align__(16) float As[BK][BM];
    __shared__ __align__(16) float Bs[BK][BN];
    const int tid = threadIdx.x;
    const int b  = blockIdx.z;
    const int i0 = blockIdx.x * BM;
    const int j0 = blockIdx.y * BN;   // 0,128,256

    const float* A  = g_attn + (size_t)b * Nn * Nn + (size_t)i0 * Nn;
    const float* Bg = g_tpg + (size_t)b * Nn * (3 * Dd) + 2 * Dd + j0;  // g rows

    float acc[TM][TN] = {};
    const int ty = tid >> 4, tx = tid & 15;

    for (int k0 = 0; k0 < Nn; k0 += BK) {
        load_trans(As, A + k0, Nn, tid);
        load_direct(Bs, Bg + (size_t)k0 * (3 * Dd), 3 * Dd, tid);
        __syncthreads();
        mma_tile(As, Bs, acc, ty, tx);
        __syncthreads();
    }

    const int r0 = i0 + ty * TM;
    const int c0 = j0 + tx * TN;
#pragma unroll
    for (int i = 0; i < TM; i++) {
        float* dst = g_od + ((size_t)b * Nn + r0 + i) * Dd + c0;
#pragma unroll
        for (int j = 0; j < TN; j++) dst[j] = acc[i][j];
    }
}

// ---------------------------------------------------------------------------
// Kernel 5: out = od @ W_out + b_out + x   (M=16384, N=768, K=384)
// grid: (128, 6)
// ---------------------------------------------------------------------------
__global__ __launch_bounds__(256, 2) void k_out(
    const float* __restrict__ x,
    const float* __restrict__ Wo, const float* __restrict__ bo,
    float* __restrict__ out)
{
    __shared__ __align__(16) float As[BK][BM];
    __shared__ __align__(16) float Bs[BK][BN];
    const int tid = threadIdx.x;
    const int m0 = blockIdx.x * BM;
    const int n0 = blockIdx.y * BN;

    float acc[TM][TN] = {};
    const int ty = tid >> 4, tx = tid & 15;

    for (int k0 = 0; k0 < Dd; k0 += BK) {
        load_trans(As, g_od + (size_t)m0 * Dd + k0, Dd, tid);
        load_direct(Bs, Wo + (size_t)k0 * Cc + n0, Cc, tid);
        __syncthreads();
        mma_tile(As, Bs, acc, ty, tx);
        __syncthreads();
    }

    const int r0 = m0 + ty * TM;
    const int c0 = n0 + tx * TN;
#pragma unroll
    for (int i = 0; i < TM; i++) {
        const size_t ro = (size_t)(r0 + i) * Cc + c0;
#pragma unroll
        for (int j = 0; j < TN; j++)
            out[ro + j] = acc[i][j] + bo[n0 % Cc + tx * TN + j] + x[ro + j];
    }
}

// ---------------------------------------------------------------------------
extern "C" void kernel_launch(void* const* d_in, const int* in_sizes, int n_in,
                              void* d_out, int out_size)
{
    const float* x  = (const float*)d_in[0];
    const float* adj = (const float*)d_in[1];
    const float* Wt = (const float*)d_in[2];
    const float* bt = (const float*)d_in[3];
    const float* Wp = (const float*)d_in[4];
    const float* bp = (const float*)d_in[5];
    const float* Wg = (const float*)d_in[6];
    const float* bg = (const float*)d_in[7];
    const float* Wo = (const float*)d_in[8];
    const float* bo = (const float*)d_in[9];
    float* out = (float*)d_out;

    dim3 blk(256);

    // 1) projections: theta|phi|g
    k_proj<<<dim3((Bz * Nn) / BM, (3 * Dd) / BN), blk>>>(x, Wt, bt, Wp, bp, Wg, bg);

    // 2) masked scores
    k_score<<<dim3(Nn / BM, Nn / BN, Bz), blk>>>(adj);

    // 3) softmax over rows
    k_softmax<<<dim3(Bz * Nn), blk>>>();

    // 4) attn @ g
    k_av<<<dim3(Nn / BM, Dd / BN, Bz), blk>>>();

    // 5) output projection + bias + residual
    k_out<<<dim3((Bz * Nn) / BM, Cc / BN), blk>>>(x, Wo, bo, out);
}

// round 3
// speedup vs baseline: 1.6170x; 1.6170x over previous
#include <cuda_runtime.h>
#include <cstdint>

// Shapes (fixed by problem)
#define Bz 16
#define Nn 1024
#define Cc 768
#define Dd 384

// GEMM tiling
#define BM 128
#define BN 128
#define BK 16
#define TM 8
#define TN 8

// Static device scratch (no allocations allowed)
__device__ __align__(16) float g_tpg[(size_t)Bz * Nn * (3 * Dd)];     // theta|phi|g, ld = 1152
__device__ __align__(16) float g_attn[(size_t)Bz * Nn * Nn];          // scores / softmax
__device__ __align__(16) float g_od[(size_t)Bz * Nn * Dd];            // attn @ g

// ---------------------------------------------------------------------------
// Loaders: tile is BM(=BN)=128 x BK=16. 2048 floats = 512 float4; 256 threads
// load 2 float4 each.
// ---------------------------------------------------------------------------

// Global [rows x K] row-major (K minor) -> S[k][m] (transposed store)
__device__ __forceinline__ void load_trans(float (*S)[BM], const float* __restrict__ g,
                                           int ldg, int tid) {
#pragma unroll
    for (int u = 0; u < 2; u++) {
        int idx = tid + u * 256;
        int m  = idx >> 2;            // 0..127
        int c4 = (idx & 3) * 4;       // 0,4,8,12
        float4 v = *(const float4*)(g + (size_t)m * ldg + c4);
        S[c4 + 0][m] = v.x;
        S[c4 + 1][m] = v.y;
        S[c4 + 2][m] = v.z;
        S[c4 + 3][m] = v.w;
    }
}

// Global [K x cols] row-major (cols minor) -> S[k][j] (direct store)
__device__ __forceinline__ void load_direct(float (*S)[BN], const float* __restrict__ g,
                                            int ldg, int tid) {
#pragma unroll
    for (int u = 0; u < 2; u++) {
        int idx = tid + u * 256;
        int k = idx >> 5;             // 0..15
        int j = (idx & 31) * 4;       // 0..124
        *(float4*)(&S[k][j]) = *(const float4*)(g + (size_t)k * ldg + j);
    }
}

// ---------------------------------------------------------------------------
// Inner product on the tile: each thread does 8x8 FMAs per k, BK=16 steps.
// ---------------------------------------------------------------------------
__device__ __forceinline__ void mma_tile(const float (*As)[BM], const float (*Bs)[BN],
                                         float acc[TM][TN], int ty, int tx) {
#pragma unroll
    for (int k = 0; k < BK; k++) {
        float4 a0 = *(const float4*)(&As[k][ty * TM]);
        float4 a1 = *(const float4*)(&As[k][ty * TM + 4]);
        float4 b0 = *(const float4*)(&Bs[k][tx * TN]);
        float4 b1 = *(const float4*)(&Bs[k][tx * TN + 4]);
        float a[TM] = {a0.x, a0.y, a0.z, a0.w, a1.x, a1.y, a1.z, a1.w};
        float b[TN] = {b0.x, b0.y, b0.z, b0.w, b1.x, b1.y, b1.z, b1.w};
#pragma unroll
        for (int i = 0; i < TM; i++)
#pragma unroll
            for (int j = 0; j < TN; j++)
                acc[i][j] = fmaf(a[i], b[j], acc[i][j]);
    }
}

// ---------------------------------------------------------------------------
// Kernel 1: fused projections.  tpg[M,1152] = x[M,768] @ [Wt|Wp|Wg] + bias
// grid: (16384/128, 1152/128) = (128, 9)
// ---------------------------------------------------------------------------
__global__ __launch_bounds__(256, 2) void k_proj(
    const float* __restrict__ x,
    const float* __restrict__ Wt, const float* __restrict__ bt,
    const float* __restrict__ Wp, const float* __restrict__ bp,
    const float* __restrict__ Wg, const float* __restrict__ bg)
{
    __shared__ __align__(16) float As[BK][BM];
    __shared__ __align__(16) float Bs[BK][BN];
    const int tid = threadIdx.x;
    const int m0 = blockIdx.x * BM;
    const int n0 = blockIdx.y * BN;      // 0..1151, tile fits in one 384-segment
    const int seg = n0 / Dd;
    const int nW  = n0 % Dd;
    const float* W    = (seg == 0) ? Wt : (seg == 1) ? Wp : Wg;
    const float* bias = (seg == 0) ? bt : (seg == 1) ? bp : bg;

    float acc[TM][TN] = {};
    const int ty = tid >> 4, tx = tid & 15;

    for (int k0 = 0; k0 < Cc; k0 += BK) {
        load_trans(As, x + (size_t)m0 * Cc + k0, Cc, tid);
        load_direct(Bs, W + (size_t)k0 * Dd + nW, Dd, tid);
        __syncthreads();
        mma_tile(As, Bs, acc, ty, tx);
        __syncthreads();
    }

    const int r0 = m0 + ty * TM;
    const int c0 = n0 + tx * TN;
#pragma unroll
    for (int i = 0; i < TM; i++) {
        float* dst = g_tpg + (size_t)(r0 + i) * (3 * Dd) + c0;
#pragma unroll
        for (int j = 0; j < TN; j++)
            dst[j] = acc[i][j] + bias[nW + tx * TN + j];
    }
}

// ---------------------------------------------------------------------------
// Kernel 2: scores.  attn[b,i,j] = (theta_b @ phi_b^T)[i,j] * adj[b,i,j]
// grid: (8, 8, 16)
// ---------------------------------------------------------------------------
__global__ __launch_bounds__(256, 2) void k_score(const float* __restrict__ adj)
{
    __shared__ __align__(16) float As[BK][BM];
    __shared__ __align__(16) float Bs[BK][BN];
    const int tid = threadIdx.x;
    const int b  = blockIdx.z;
    const int i0 = blockIdx.x * BM;
    const int j0 = blockIdx.y * BN;

    const float* th = g_tpg + ((size_t)b * Nn + i0) * (3 * Dd);         // theta rows
    const float* ph = g_tpg + ((size_t)b * Nn + j0) * (3 * Dd) + Dd;    // phi rows

    float acc[TM][TN] = {};
    const int ty = tid >> 4, tx = tid & 15;

    for (int k0 = 0; k0 < Dd; k0 += BK) {
        load_trans(As, th + k0, 3 * Dd, tid);
        load_trans((float(*)[BM])Bs, ph + k0, 3 * Dd, tid);
        __syncthreads();
        mma_tile(As, Bs, acc, ty, tx);
        __syncthreads();
    }

    const size_t base = (size_t)b * Nn * Nn;
    const int r0 = i0 + ty * TM;
    const int c0 = j0 + tx * TN;
#pragma unroll
    for (int i = 0; i < TM; i++) {
        const size_t ro = base + (size_t)(r0 + i) * Nn + c0;
#pragma unroll
        for (int j = 0; j < TN; j++)
            g_attn[ro + j] = acc[i][j] * adj[ro + j];
    }
}

// ---------------------------------------------------------------------------
// Kernel 3: row softmax over last dim (1024). One block per row, 256 threads,
// one float4 per thread.
// ---------------------------------------------------------------------------
__global__ __launch_bounds__(256) void k_softmax()
{
    const size_t row = blockIdx.x;
    float4* p = (float4*)(g_attn + row * Nn);
    float4 v = p[threadIdx.x];

    float m = fmaxf(fmaxf(v.x, v.y), fmaxf(v.z, v.w));
#pragma unroll
    for (int o = 16; o; o >>= 1) m = fmaxf(m, __shfl_xor_sync(0xffffffffu, m, o));
    __shared__ float red[8];
    const int warp = threadIdx.x >> 5;
    if ((threadIdx.x & 31) == 0) red[warp] = m;
    __syncthreads();
    float bm = red[0];
#pragma unroll
    for (int i = 1; i < 8; i++) bm = fmaxf(bm, red[i]);
    __syncthreads();

    v.x = __expf(v.x - bm);
    v.y = __expf(v.y - bm);
    v.z = __expf(v.z - bm);
    v.w = __expf(v.w - bm);
    float s = v.x + v.y + v.z + v.w;
#pragma unroll
    for (int o = 16; o; o >>= 1) s += __shfl_xor_sync(0xffffffffu, s, o);
    if ((threadIdx.x & 31) == 0) red[warp] = s;
    __syncthreads();
    float tot = red[0];
#pragma unroll
    for (int i = 1; i < 8; i++) tot += red[i];

    const float inv = 1.0f / tot;
    v.x *= inv; v.y *= inv; v.z *= inv; v.w *= inv;
    p[threadIdx.x] = v;
}

// ---------------------------------------------------------------------------
// Kernel 4: od[b,i,:] = attn[b,i,:] @ g_b   (M=1024, N=384, K=1024 per batch)
// grid: (8, 3, 16)
// ---------------------------------------------------------------------------
__global__ __launch_bounds__(256, 2) void k_av()
{
    __shared__ __align__(16) float As[BK][BM];
    __shared__ __align__(16) float Bs[BK][BN];
    const int tid = threadIdx.x;
    const int b  = blockIdx.z;
    const int i0 = blockIdx.x * BM;
    const int j0 = blockIdx.y * BN;   // 0,128,256

    const float* A  = g_attn + (size_t)b * Nn * Nn + (size_t)i0 * Nn;
    const float* Bg = g_tpg + (size_t)b * Nn * (3 * Dd) + 2 * Dd + j0;  // g rows

    float acc[TM][TN] = {};
    const int ty = tid >> 4, tx = tid & 15;

    for (int k0 = 0; k0 < Nn; k0 += BK) {
        load_trans(As, A + k0, Nn, tid);
        load_direct(Bs, Bg + (size_t)k0 * (3 * Dd), 3 * Dd, tid);
        __syncthreads();
        mma_tile(As, Bs, acc, ty, tx);
        __syncthreads();
    }

    const int r0 = i0 + ty * TM;
    const int c0 = j0 + tx * TN;
#pragma unroll
    for (int i = 0; i < TM; i++) {
        float* dst = g_od + ((size_t)b * Nn + r0 + i) * Dd + c0;
#pragma unroll
        for (int j = 0; j < TN; j++) dst[j] = acc[i][j];
    }
}

// ---------------------------------------------------------------------------
// Kernel 5: out = od @ W_out + b_out + x   (M=16384, N=768, K=384)
// grid: (128, 6)
// ---------------------------------------------------------------------------
__global__ __launch_bounds__(256, 2) void k_out(
    const float* __restrict__ x,
    const float* __restrict__ Wo, const float* __restrict__ bo,
    float* __restrict__ out)
{
    __shared__ __align__(16) float As[BK][BM];
    __shared__ __align__(16) float Bs[BK][BN];
    const int tid = threadIdx.x;
    const int m0 = blockIdx.x * BM;
    const int n0 = blockIdx.y * BN;

    float acc[TM][TN] = {};
    const int ty = tid >> 4, tx = tid & 15;

    for (int k0 = 0; k0 < Dd; k0 += BK) {
        load_trans(As, g_od + (size_t)m0 * Dd + k0, Dd, tid);
        load_direct(Bs, Wo + (size_t)k0 * Cc + n0, Cc, tid);
        __syncthreads();
        mma_tile(As, Bs, acc, ty, tx);
        __syncthreads();
    }

    const int r0 = m0 + ty * TM;
    const int c0 = n0 + tx * TN;
#pragma unroll
    for (int i = 0; i < TM; i++) {
        const size_t ro = (size_t)(r0 + i) * Cc + c0;
#pragma unroll
        for (int j = 0; j < TN; j++)
            out[ro + j] = acc[i][j] + bo[n0 % Cc + tx * TN + j] + x[ro + j];
    }
}

// ---------------------------------------------------------------------------
extern "C" void kernel_launch(void* const* d_in, const int* in_sizes, int n_in,
                              void* d_out, int out_size)
{
    const float* x  = (const float*)d_in[0];
    const float* adj = (const float*)d_in[1];
    const float* Wt = (const float*)d_in[2];
    const float* bt = (const float*)d_in[3];
    const float* Wp = (const float*)d_in[4];
    const float* bp = (const float*)d_in[5];
    const float* Wg = (const float*)d_in[6];
    const float* bg = (const float*)d_in[7];
    const float* Wo = (const float*)d_in[8];
    const float* bo = (const float*)d_in[9];
    float* out = (float*)d_out;

    dim3 blk(256);

    // 1) projections: theta|phi|g
    k_proj<<<dim3((Bz * Nn) / BM, (3 * Dd) / BN), blk>>>(x, Wt, bt, Wp, bp, Wg, bg);

    // 2) masked scores
    k_score<<<dim3(Nn / BM, Nn / BN, Bz), blk>>>(adj);

    // 3) softmax over rows
    k_softmax<<<dim3(Bz * Nn), blk>>>();

    // 4) attn @ g
    k_av<<<dim3(Nn / BM, Dd / BN, Bz), blk>>>();

    // 5) output projection + bias + residual
    k_out<<<dim3((Bz * Nn) / BM, Cc / BN), blk>>>(x, Wo, bo, out);
}

// round 4
// speedup vs baseline: 1.6178x; 1.0005x over previous
#include <cuda_runtime.h>
#include <cstdint>

// Shapes (fixed by problem)
#define Bz 16
#define Nn 1024
#define Cc 768
#define Dd 384

// GEMM tiling
#define BM 128
#define BN 128
#define BK 16
#define TM 8
#define TN 8

// Static device scratch (no allocations allowed)
__device__ __align__(16) float g_tpg[(size_t)Bz * Nn * (3 * Dd)];     // theta|phi|g, ld = 1152
__device__ __align__(16) float g_attn[(size_t)Bz * Nn * Nn];          // scores / softmax
__device__ __align__(16) float g_od[(size_t)Bz * Nn * Dd];            // attn @ g

// ---------------------------------------------------------------------------
// Loaders: tile is BM(=BN)=128 x BK=16. 2048 floats = 512 float4; 256 threads
// load 2 float4 each.
// ---------------------------------------------------------------------------

// Global [rows x K] row-major (K minor) -> S[k][m] (transposed store)
__device__ __forceinline__ void load_trans(float (*S)[BM], const float* __restrict__ g,
                                           int ldg, int tid) {
#pragma unroll
    for (int u = 0; u < 2; u++) {
        int idx = tid + u * 256;
        int m  = idx >> 2;            // 0..127
        int c4 = (idx & 3) * 4;       // 0,4,8,12
        float4 v = *(const float4*)(g + (size_t)m * ldg + c4);
        S[c4 + 0][m] = v.x;
        S[c4 + 1][m] = v.y;
        S[c4 + 2][m] = v.z;
        S[c4 + 3][m] = v.w;
    }
}

// Global [K x cols] row-major (cols minor) -> S[k][j] (direct store)
__device__ __forceinline__ void load_direct(float (*S)[BN], const float* __restrict__ g,
                                            int ldg, int tid) {
#pragma unroll
    for (int u = 0; u < 2; u++) {
        int idx = tid + u * 256;
        int k = idx >> 5;             // 0..15
        int j = (idx & 31) * 4;       // 0..124
        *(float4*)(&S[k][j]) = *(const float4*)(g + (size_t)k * ldg + j);
    }
}

// ---------------------------------------------------------------------------
// Inner product on the tile: each thread does 8x8 FMAs per k, BK=16 steps.
// ---------------------------------------------------------------------------
__device__ __forceinline__ void mma_tile(const float (*As)[BM], const float (*Bs)[BN],
                                         float acc[TM][TN], int ty, int tx) {
#pragma unroll
    for (int k = 0; k < BK; k++) {
        float4 a0 = *(const float4*)(&As[k][ty * TM]);
        float4 a1 = *(const float4*)(&As[k][ty * TM + 4]);
        float4 b0 = *(const float4*)(&Bs[k][tx * TN]);
        float4 b1 = *(const float4*)(&Bs[k][tx * TN + 4]);
        float a[TM] = {a0.x, a0.y, a0.z, a0.w, a1.x, a1.y, a1.z, a1.w};
        float b[TN] = {b0.x, b0.y, b0.z, b0.w, b1.x, b1.y, b1.z, b1.w};
#pragma unroll
        for (int i = 0; i < TM; i++)
#pragma unroll
            for (int j = 0; j < TN; j++)
                acc[i][j] = fmaf(a[i], b[j], acc[i][j]);
    }
}

// ---------------------------------------------------------------------------
// Kernel 1: fused projections.  tpg[M,1152] = x[M,768] @ [Wt|Wp|Wg] + bias
// grid: (16384/128, 1152/128) = (128, 9)
// ---------------------------------------------------------------------------
__global__ __launch_bounds__(256, 2) void k_proj(
    const float* __restrict__ x,
    const float* __restrict__ Wt, const float* __restrict__ bt,
    const float* __restrict__ Wp, const float* __restrict__ bp,
    const float* __restrict__ Wg, const float* __restrict__ bg)
{
    __shared__ __align__(16) float As[BK][BM];
    __shared__ __align__(16) float Bs[BK][BN];
    const int tid = threadIdx.x;
    const int m0 = blockIdx.x * BM;
    const int n0 = blockIdx.y * BN;      // 0..1151, tile fits in one 384-segment
    const int seg = n0 / Dd;
    const int nW  = n0 % Dd;
    const float* W    = (seg == 0) ? Wt : (seg == 1) ? Wp : Wg;
    const float* bias = (seg == 0) ? bt : (seg == 1) ? bp : bg;

    float acc[TM][TN] = {};
    const int ty = tid >> 4, tx = tid & 15;

    for (int k0 = 0; k0 < Cc; k0 += BK) {
        load_trans(As, x + (size_t)m0 * Cc + k0, Cc, tid);
        load_direct(Bs, W + (size_t)k0 * Dd + nW, Dd, tid);
        __syncthreads();
        mma_tile(As, Bs, acc, ty, tx);
        __syncthreads();
    }

    const int r0 = m0 + ty * TM;
    const int c0 = n0 + tx * TN;
#pragma unroll
    for (int i = 0; i < TM; i++) {
        float* dst = g_tpg + (size_t)(r0 + i) * (3 * Dd) + c0;
#pragma unroll
        for (int j = 0; j < TN; j++)
            dst[j] = acc[i][j] + bias[nW + tx * TN + j];
    }
}

// ---------------------------------------------------------------------------
// Kernel 2: scores.  attn[b,i,j] = (theta_b @ phi_b^T)[i,j] * adj[b,i,j]
// grid: (8, 8, 16)
// ---------------------------------------------------------------------------
__global__ __launch_bounds__(256, 2) void k_score(const float* __restrict__ adj)
{
    __shared__ __align__(16) float As[BK][BM];
    __shared__ __align__(16) float Bs[BK][BN];
    const int tid = threadIdx.x;
    const int b  = blockIdx.z;
    const int i0 = blockIdx.x * BM;
    const int j0 = blockIdx.y * BN;

    const float* th = g_tpg + ((size_t)b * Nn + i0) * (3 * Dd);         // theta rows
    const float* ph = g_tpg + ((size_t)b * Nn + j0) * (3 * Dd) + Dd;    // phi rows

    float acc[TM][TN] = {};
    const int ty = tid >> 4, tx = tid & 15;

    for (int k0 = 0; k0 < Dd; k0 += BK) {
        load_trans(As, th + k0, 3 * Dd, tid);
        load_trans((float(*)[BM])Bs, ph + k0, 3 * Dd, tid);
        __syncthreads();
        mma_tile(As, Bs, acc, ty, tx);
        __syncthreads();
    }

    const size_t base = (size_t)b * Nn * Nn;
    const int r0 = i0 + ty * TM;
    const int c0 = j0 + tx * TN;
#pragma unroll
    for (int i = 0; i < TM; i++) {
        const size_t ro = base + (size_t)(r0 + i) * Nn + c0;
#pragma unroll
        for (int j = 0; j < TN; j++)
            g_attn[ro + j] = acc[i][j] * adj[ro + j];
    }
}

// ---------------------------------------------------------------------------
// Kernel 3: row softmax over last dim (1024). One block per row, 256 threads,
// one float4 per thread.
// ---------------------------------------------------------------------------
__global__ __launch_bounds__(256) void k_softmax()
{
    const size_t row = blockIdx.x;
    float4* p = (float4*)(g_attn + row * Nn);
    float4 v = p[threadIdx.x];

    float m = fmaxf(fmaxf(v.x, v.y), fmaxf(v.z, v.w));
#pragma unroll
    for (int o = 16; o; o >>= 1) m = fmaxf(m, __shfl_xor_sync(0xffffffffu, m, o));
    __shared__ float red[8];
    const int warp = threadIdx.x >> 5;
    if ((threadIdx.x & 31) == 0) red[warp] = m;
    __syncthreads();
    float bm = red[0];
#pragma unroll
    for (int i = 1; i < 8; i++) bm = fmaxf(bm, red[i]);
    __syncthreads();

    v.x = __expf(v.x - bm);
    v.y = __expf(v.y - bm);
    v.z = __expf(v.z - bm);
    v.w = __expf(v.w - bm);
    float s = v.x + v.y + v.z + v.w;
#pragma unroll
    for (int o = 16; o; o >>= 1) s += __shfl_xor_sync(0xffffffffu, s, o);
    if ((threadIdx.x & 31) == 0) red[warp] = s;
    __syncthreads();
    float tot = red[0];
#pragma unroll
    for (int i = 1; i < 8; i++) tot += red[i];

    const float inv = 1.0f / tot;
    v.x *= inv; v.y *= inv; v.z *= inv; v.w *= inv;
    p[threadIdx.x] = v;
}

// ---------------------------------------------------------------------------
// Kernel 4: od[b,i,:] = attn[b,i,:] @ g_b   (M=1024, N=384, K=1024 per batch)
// grid: (8, 3, 16)
// ---------------------------------------------------------------------------
__global__ __launch_bounds__(256, 2) void k_av()
{
    __shared__ __align__(16) float As[BK][BM];
    __shared__ __align__(16) float Bs[BK][BN];
    const int tid = threadIdx.x;
    const int b  = blockIdx.z;
    const int i0 = blockIdx.x * BM;
    const int j0 = blockIdx.y * BN;   // 0,128,256

    const float* A  = g_attn + (size_t)b * Nn * Nn + (size_t)i0 * Nn;
    const float* Bg = g_tpg + (size_t)b * Nn * (3 * Dd) + 2 * Dd + j0;  // g rows

    float acc[TM][TN] = {};
    const int ty = tid >> 4, tx = tid & 15;

    for (int k0 = 0; k0 < Nn; k0 += BK) {
        load_trans(As, A + k0, Nn, tid);
        load_direct(Bs, Bg + (size_t)k0 * (3 * Dd), 3 * Dd, tid);
        __syncthreads();
        mma_tile(As, Bs, acc, ty, tx);
        __syncthreads();
    }

    const int r0 = i0 + ty * TM;
    const int c0 = j0 + tx * TN;
#pragma unroll
    for (int i = 0; i < TM; i++) {
        float* dst = g_od + ((size_t)b * Nn + r0 + i) * Dd + c0;
#pragma unroll
        for (int j = 0; j < TN; j++) dst[j] = acc[i][j];
    }
}

// ---------------------------------------------------------------------------
// Kernel 5: out = od @ W_out + b_out + x   (M=16384, N=768, K=384)
// grid: (128, 6)
// ---------------------------------------------------------------------------
__global__ __launch_bounds__(256, 2) void k_out(
    const float* __restrict__ x,
    const float* __restrict__ Wo, const float* __restrict__ bo,
    float* __restrict__ out)
{
    __shared__ __align__(16) float As[BK][BM];
    __shared__ __align__(16) float Bs[BK][BN];
    const int tid = threadIdx.x;
    const int m0 = blockIdx.x * BM;
    const int n0 = blockIdx.y * BN;

    float acc[TM][TN] = {};
    const int ty = tid >> 4, tx = tid & 15;

    for (int k0 = 0; k0 < Dd; k0 += BK) {
        load_trans(As, g_od + (size_t)m0 * Dd + k0, Dd, tid);
        load_direct(Bs, Wo + (size_t)k0 * Cc + n0, Cc, tid);
        __syncthreads();
        mma_tile(As, Bs, acc, ty, tx);
        __syncthreads();
    }

    const int r0 = m0 + ty * TM;
    const int c0 = n0 + tx * TN;
#pragma unroll
    for (int i = 0; i < TM; i++) {
        const size_t ro = (size_t)(r0 + i) * Cc + c0;
#pragma unroll
        for (int j = 0; j < TN; j++)
            out[ro + j] = acc[i][j] + bo[n0 % Cc + tx * TN + j] + x[ro + j];
    }
}

// ---------------------------------------------------------------------------
extern "C" void kernel_launch(void* const* d_in, const int* in_sizes, int n_in,
                              void* d_out, int out_size)
{
    const float* x  = (const float*)d_in[0];
    const float* adj = (const float*)d_in[1];
    const float* Wt = (const float*)d_in[2];
    const float* bt = (const float*)d_in[3];
    const float* Wp = (const float*)d_in[4];
    const float* bp = (const float*)d_in[5];
    const float* Wg = (const float*)d_in[6];
    const float* bg = (const float*)d_in[7];
    const float* Wo = (const float*)d_in[8];
    const float* bo = (const float*)d_in[9];
    float* out = (float*)d_out;

    dim3 blk(256);

    // 1) projections: theta|phi|g
    k_proj<<<dim3((Bz * Nn) / BM, (3 * Dd) / BN), blk>>>(x, Wt, bt, Wp, bp, Wg, bg);

    // 2) masked scores
    k_score<<<dim3(Nn / BM, Nn / BN, Bz), blk>>>(adj);

    // 3) softmax over rows
    k_softmax<<<dim3(Bz * Nn), blk>>>();

    // 4) attn @ g
    k_av<<<dim3(Nn / BM, Dd / BN, Bz), blk>>>();

    // 5) output projection + bias + residual
    k_out<<<dim3((Bz * Nn) / BM, Cc / BN), blk>>>(x, Wo, bo, out);
}